// round 11
// baseline (speedup 1.0000x reference)
#include <cuda_runtime.h>
#include <cuda_fp16.h>
#include <cstdint>

// Problem constants (match reference)
#define N_USERS 200000
#define N_ITEMS 400000
#define N_NODES 600000
#define EMB_DIM 128
#define N_EDGES 3000000
#define VEC4_PER_ROW 32
#define TOTAL_F ((size_t)N_NODES * EMB_DIM)   // 76.8M elems
#define TOTAL_V4 (TOTAL_F / 4)

#define SCAN_BLOCK 1024
#define N_SCAN_BLOCKS ((N_NODES + SCAN_BLOCK - 1) / SCAN_BLOCK)  // 586

// Static scratch (allowed: __device__ globals; zero-init on load)
__device__ __align__(256) __half g_bufX[TOTAL_F];   // fp16 inputs, 153.6 MB
__device__ __align__(256) __half g_bufA[TOTAL_F];
__device__ __align__(256) __half g_bufB[TOTAL_F];
__device__ int  g_count[N_NODES];        // re-zeroed every replay by scan
__device__ int  g_offsetG[N_NODES + 1];  // GLOBAL exclusive scan
__device__ int  g_pos[N_NODES];
__device__ int  g_ticket;                // dynamic block ordering
__device__ int  g_scanState[SCAN_BLOCK]; // lookback: flag<<30 | value
__device__ int2 g_pair[N_EDGES];         // (col, val-as-int), CSR order

// ---------------------------------------------------------------------------
// Launch 1: histogram + fp32->fp16 conversion + scan-state/ticket reset
// ---------------------------------------------------------------------------
__global__ void hist_convert_kernel(const int* __restrict__ rows,
                                    int* __restrict__ count,
                                    const float4* __restrict__ user,
                                    const float4* __restrict__ item,
                                    uint2* __restrict__ X2) {
    size_t tid = (size_t)blockIdx.x * blockDim.x + threadIdx.x;
    if (tid < SCAN_BLOCK) g_scanState[tid] = 0;   // reset lookback state
    if (tid == 0) g_ticket = 0;                   // reset ticket counter
    if (tid < N_EDGES) atomicAdd(&count[rows[tid]], 1);

    const size_t user_v4 = (size_t)N_USERS * VEC4_PER_ROW;
    size_t stride = (size_t)gridDim.x * blockDim.x;
    for (size_t i = tid; i < TOTAL_V4; i += stride) {
        float4 v = (i < user_v4) ? __ldcs(user + i) : __ldcs(item + i - user_v4);
        __half2 h0 = __floats2half2_rn(v.x, v.y);
        __half2 h1 = __floats2half2_rn(v.z, v.w);
        uint2 raw;
        raw.x = *reinterpret_cast<unsigned*>(&h0);
        raw.y = *reinterpret_cast<unsigned*>(&h1);
        __stcs(X2 + i, raw);   // streaming
    }
}

// ---------------------------------------------------------------------------
// Launch 2: single-pass scan, decoupled lookback with TICKET ordering.
// vbid = ticket acquisition order == scheduling order -> every predecessor
// is resident; no deadlock under work-stealing schedulers.
// ---------------------------------------------------------------------------
#define FLAG_AGG 1
#define FLAG_INC 2
#define VAL_MASK ((1 << 30) - 1)

__global__ void scan_kernel(int* __restrict__ count,
                            int* __restrict__ offsetG,
                            int* __restrict__ pos) {
    __shared__ int sh[SCAN_BLOCK];
    __shared__ int sh_vbid;
    __shared__ int sh_base;

    if (threadIdx.x == 0) sh_vbid = atomicAdd(&g_ticket, 1);
    __syncthreads();
    int bid = sh_vbid;

    int i = bid * SCAN_BLOCK + threadIdx.x;
    int v = (i < N_NODES) ? count[i] : 0;
    if (i < N_NODES) count[i] = 0;   // restore replay invariant
    sh[threadIdx.x] = v;
    __syncthreads();
    #pragma unroll
    for (int d = 1; d < SCAN_BLOCK; d <<= 1) {
        int t = (threadIdx.x >= d) ? sh[threadIdx.x - d] : 0;
        __syncthreads();
        sh[threadIdx.x] += t;
        __syncthreads();
    }
    int incl = sh[threadIdx.x];

    if (threadIdx.x == SCAN_BLOCK - 1) {
        int agg = incl;   // block total
        int exclusive = 0;
        if (bid == 0) {
            __threadfence();
            atomicExch(&g_scanState[0], (FLAG_INC << 30) | agg);
        } else {
            __threadfence();
            atomicExch(&g_scanState[bid], (FLAG_AGG << 30) | agg);
            int j = bid - 1;
            int running = 0;
            while (true) {
                int s = atomicAdd(&g_scanState[j], 0);   // atomic read
                int f = (unsigned)s >> 30;
                if (f == 0) { __nanosleep(40); continue; }
                running += (s & VAL_MASK);
                if (f == FLAG_INC) break;
                --j;
            }
            exclusive = running;
            __threadfence();
            atomicExch(&g_scanState[bid], (FLAG_INC << 30) | (exclusive + agg));
        }
        sh_base = exclusive;
        if (bid == N_SCAN_BLOCKS - 1) offsetG[N_NODES] = N_EDGES;
    }
    __syncthreads();

    if (i < N_NODES) {
        int off = sh_base + incl - v;   // global exclusive
        offsetG[i] = off;
        pos[i] = off;
    }
}

// ---------------------------------------------------------------------------
// Launch 3: permute edges into CSR order
// ---------------------------------------------------------------------------
__global__ void permute_kernel(const int* __restrict__ rows,
                               const int* __restrict__ cols,
                               const float* __restrict__ vals,
                               int* __restrict__ pos,
                               int2* __restrict__ pair) {
    int e = blockIdx.x * blockDim.x + threadIdx.x;
    if (e >= N_EDGES) return;
    int r = rows[e];
    int p = atomicAdd(&pos[r], 1);
    int2 pr;
    pr.x = cols[e];
    pr.y = __float_as_int(vals[e]);
    __stcs(pair + p, pr);    // streaming scatter
}

// ---------------------------------------------------------------------------
// Gather: 32B (256-bit) load with L2 evict_last (pins source rows in L2),
// unpack 16 halfs, FMA into 16 fp32 accumulators.
// ---------------------------------------------------------------------------
__device__ __forceinline__ void gather_acc(const __half* __restrict__ srcH,
                                           int col, int sub, float v,
                                           float* acc) {
    const char* p = reinterpret_cast<const char*>(srcH)
                    + ((size_t)col << 8) + (sub << 5);
    uint32_t q0, q1, q2, q3, q4, q5, q6, q7;
    asm volatile(
        "ld.global.nc.L2::evict_last.v8.b32 {%0,%1,%2,%3,%4,%5,%6,%7}, [%8];"
        : "=r"(q0), "=r"(q1), "=r"(q2), "=r"(q3),
          "=r"(q4), "=r"(q5), "=r"(q6), "=r"(q7)
        : "l"(p));
    uint32_t q[8] = {q0, q1, q2, q3, q4, q5, q6, q7};
    #pragma unroll
    for (int i = 0; i < 8; ++i) {
        __half2 h = *reinterpret_cast<__half2*>(&q[i]);
        float2 f = __half22float2(h);
        acc[2 * i]     += v * f.x;
        acc[2 * i + 1] += v * f.y;
    }
}

__device__ __forceinline__ void unpack16(uint4 lo, uint4 hi, float* f) {
    uint32_t q[8] = {lo.x, lo.y, lo.z, lo.w, hi.x, hi.y, hi.z, hi.w};
    #pragma unroll
    for (int i = 0; i < 8; ++i) {
        __half2 h = *reinterpret_cast<__half2*>(&q[i]);
        float2 t = __half22float2(h);
        f[2 * i] = t.x;
        f[2 * i + 1] = t.y;
    }
}

// ---------------------------------------------------------------------------
// Launches 4-6: pull SpMM. One 8-lane group per row; lane owns 16 elements
// (32B fp16). Gather via LDG.256 + L2::evict_last, unrolled x4. fp32 accum.
// FUSED (layer 3): out = 0.25*(x0_fp32 + A + B + y)
// ---------------------------------------------------------------------------
template <bool FUSED>
__global__ void __launch_bounds__(256)
spmm_kernel(const int* __restrict__ offsetG,
            const int2* __restrict__ pair,
            const __half* __restrict__ xH,    // gather src (fp16, L2-pinned)
            __half* __restrict__ dstH,        // layer output (fp16)
            const float4* __restrict__ u,     // FUSED: user embs fp32
            const float4* __restrict__ it,    // FUSED: item embs fp32
            const __half* __restrict__ accA,  // FUSED: layer-1 out
            const __half* __restrict__ accB,  // FUSED: layer-2 out
            float4* __restrict__ out) {       // FUSED: final out fp32
    int sub = threadIdx.x & 7;                            // lane within group
    int r = (blockIdx.x * blockDim.x + threadIdx.x) >> 3; // group id = row
    if (r >= N_NODES) return;

    int j = __ldg(offsetG + r);
    int end = __ldg(offsetG + r + 1);

    float acc[16];
    #pragma unroll
    for (int k = 0; k < 16; ++k) acc[k] = 0.f;

    // 4 independent gathers in flight per group
    #pragma unroll 1
    for (; j + 4 <= end; j += 4) {
        int2 e0 = __ldcs(pair + j);
        int2 e1 = __ldcs(pair + j + 1);
        int2 e2 = __ldcs(pair + j + 2);
        int2 e3 = __ldcs(pair + j + 3);
        gather_acc(xH, e0.x, sub, __int_as_float(e0.y), acc);
        gather_acc(xH, e1.x, sub, __int_as_float(e1.y), acc);
        gather_acc(xH, e2.x, sub, __int_as_float(e2.y), acc);
        gather_acc(xH, e3.x, sub, __int_as_float(e3.y), acc);
    }
    #pragma unroll 1
    for (; j < end; ++j) {
        int2 e0 = __ldcs(pair + j);
        gather_acc(xH, e0.x, sub, __int_as_float(e0.y), acc);
    }

    if (FUSED) {
        const uint4* aRow = reinterpret_cast<const uint4*>(accA + (size_t)r * EMB_DIM);
        const uint4* bRow = reinterpret_cast<const uint4*>(accB + (size_t)r * EMB_DIM);
        float a[16], b[16];
        unpack16(__ldcs(aRow + 2 * sub), __ldcs(aRow + 2 * sub + 1), a);
        unpack16(__ldcs(bRow + 2 * sub), __ldcs(bRow + 2 * sub + 1), b);

        const float4* xr = (r < N_USERS)
                               ? (u + (size_t)r * VEC4_PER_ROW)
                               : (it + (size_t)(r - N_USERS) * VEC4_PER_ROW);
        float4* orow = out + (size_t)r * VEC4_PER_ROW + 4 * sub;
        #pragma unroll
        for (int q = 0; q < 4; ++q) {
            float4 x0 = __ldcs(xr + 4 * sub + q);
            float4 o;
            o.x = 0.25f * (x0.x + a[4 * q + 0] + b[4 * q + 0] + acc[4 * q + 0]);
            o.y = 0.25f * (x0.y + a[4 * q + 1] + b[4 * q + 1] + acc[4 * q + 1]);
            o.z = 0.25f * (x0.z + a[4 * q + 2] + b[4 * q + 2] + acc[4 * q + 2]);
            o.w = 0.25f * (x0.w + a[4 * q + 3] + b[4 * q + 3] + acc[4 * q + 3]);
            __stcs(orow + q, o);
        }
    } else {
        uint32_t q[8];
        #pragma unroll
        for (int i = 0; i < 8; ++i) {
            __half2 h = __floats2half2_rn(acc[2 * i], acc[2 * i + 1]);
            q[i] = *reinterpret_cast<unsigned*>(&h);
        }
        uint4* drow = reinterpret_cast<uint4*>(dstH + (size_t)r * EMB_DIM) + 2 * sub;
        __stcs(drow, make_uint4(q[0], q[1], q[2], q[3]));
        __stcs(drow + 1, make_uint4(q[4], q[5], q[6], q[7]));
    }
}

extern "C" void kernel_launch(void* const* d_in, const int* in_sizes, int n_in,
                              void* d_out, int out_size) {
    const float4* emb_user = (const float4*)d_in[0];
    const float4* emb_item = (const float4*)d_in[1];
    const int* edge_row = (const int*)d_in[2];
    const int* edge_col = (const int*)d_in[3];
    const float* edge_val = (const float*)d_in[4];
    float4* out = (float4*)d_out;

    __half *X, *A, *B;
    int *count_, *offsetG_, *pos_;
    int2 *pair_;
    cudaGetSymbolAddress((void**)&X, g_bufX);
    cudaGetSymbolAddress((void**)&A, g_bufA);
    cudaGetSymbolAddress((void**)&B, g_bufB);
    cudaGetSymbolAddress((void**)&count_, g_count);
    cudaGetSymbolAddress((void**)&offsetG_, g_offsetG);
    cudaGetSymbolAddress((void**)&pos_, g_pos);
    cudaGetSymbolAddress((void**)&pair_, g_pair);

    const int T = 256;
    const int gridEdge = (N_EDGES + T - 1) / T;
    const int TS = 256;                                   // 32 rows per block
    const int gridRow = (int)(((size_t)N_NODES * 8 + TS - 1) / TS);

    // 1: histogram + fp16 conversion + lookback-state/ticket reset
    hist_convert_kernel<<<gridEdge, T>>>(edge_row, count_,
                                         emb_user, emb_item, (uint2*)X);
    // 2: single-pass global scan (ticket-ordered decoupled lookback)
    scan_kernel<<<N_SCAN_BLOCKS, SCAN_BLOCK>>>(count_, offsetG_, pos_);
    // 3: permute edges into CSR order
    permute_kernel<<<gridEdge, T>>>(edge_row, edge_col, edge_val, pos_, pair_);

    // 4: Layer 1: gather X -> A
    spmm_kernel<false><<<gridRow, TS>>>(offsetG_, pair_, X, A,
                                        nullptr, nullptr, nullptr, nullptr,
                                        nullptr);
    // 5: Layer 2: gather A -> B
    spmm_kernel<false><<<gridRow, TS>>>(offsetG_, pair_, A, B,
                                        nullptr, nullptr, nullptr, nullptr,
                                        nullptr);
    // 6: Layer 3 fused: gather B, out = 0.25*(x0 + A + B + y)
    spmm_kernel<true><<<gridRow, TS>>>(offsetG_, pair_, B, nullptr,
                                       emb_user, emb_item, A, B, out);
}

// round 12
// speedup vs baseline: 1.0403x; 1.0403x over previous
#include <cuda_runtime.h>
#include <cuda_fp16.h>
#include <cstdint>

// Problem constants (match reference)
#define N_USERS 200000
#define N_ITEMS 400000
#define N_NODES 600000
#define EMB_DIM 128
#define N_EDGES 3000000
#define VEC4_PER_ROW 32
#define TOTAL_F ((size_t)N_NODES * EMB_DIM)   // 76.8M elems
#define TOTAL_V4 (TOTAL_F / 4)

#define SCAN_BLOCK 1024
#define N_SCAN_BLOCKS ((N_NODES + SCAN_BLOCK - 1) / SCAN_BLOCK)  // 586

// Static scratch (allowed: __device__ globals; zero-init on load)
__device__ __align__(256) __half g_bufX[TOTAL_F];   // fp16 inputs, 153.6 MB
__device__ __align__(256) __half g_bufA[TOTAL_F];
__device__ __align__(256) __half g_bufB[TOTAL_F];
__device__ int  g_count[N_NODES];    // re-zeroed every replay by scan1
__device__ int  g_offsetL[N_NODES];  // block-local exclusive scan
__device__ int  g_pos[N_NODES];
__device__ int  g_bsum[SCAN_BLOCK];  // >= N_SCAN_BLOCKS
__device__ int2 g_pair[N_EDGES];     // (col, val-as-int), CSR order

// ---------------------------------------------------------------------------
// Launch 1: histogram + fp32->fp16 input conversion (grid-stride)
// ---------------------------------------------------------------------------
__global__ void hist_convert_kernel(const int* __restrict__ rows,
                                    int* __restrict__ count,
                                    const float4* __restrict__ user,
                                    const float4* __restrict__ item,
                                    uint2* __restrict__ X2) {
    size_t tid = (size_t)blockIdx.x * blockDim.x + threadIdx.x;
    if (tid < N_EDGES) atomicAdd(&count[rows[tid]], 1);

    const size_t user_v4 = (size_t)N_USERS * VEC4_PER_ROW;
    size_t stride = (size_t)gridDim.x * blockDim.x;
    for (size_t i = tid; i < TOTAL_V4; i += stride) {
        float4 v = (i < user_v4) ? __ldcs(user + i) : __ldcs(item + i - user_v4);
        __half2 h0 = __floats2half2_rn(v.x, v.y);
        __half2 h1 = __floats2half2_rn(v.z, v.w);
        uint2 raw;
        raw.x = *reinterpret_cast<unsigned*>(&h0);
        raw.y = *reinterpret_cast<unsigned*>(&h1);
        __stcs(X2 + i, raw);   // streaming
    }
}

// ---------------------------------------------------------------------------
// Launch 2: block-local exclusive scan; zeroes count; seeds pos
// ---------------------------------------------------------------------------
__global__ void scan1_kernel(int* __restrict__ count,
                             int* __restrict__ offsetL,
                             int* __restrict__ pos,
                             int* __restrict__ bsum) {
    __shared__ int sh[SCAN_BLOCK];
    int i = blockIdx.x * SCAN_BLOCK + threadIdx.x;
    int v = (i < N_NODES) ? count[i] : 0;
    if (i < N_NODES) count[i] = 0;   // restore replay invariant
    sh[threadIdx.x] = v;
    __syncthreads();
    #pragma unroll
    for (int d = 1; d < SCAN_BLOCK; d <<= 1) {
        int t = (threadIdx.x >= d) ? sh[threadIdx.x - d] : 0;
        __syncthreads();
        sh[threadIdx.x] += t;
        __syncthreads();
    }
    if (i < N_NODES) {
        int excl = sh[threadIdx.x] - v;
        offsetL[i] = excl;
        pos[i] = excl;
    }
    if (threadIdx.x == SCAN_BLOCK - 1) bsum[blockIdx.x] = sh[SCAN_BLOCK - 1];
}

// ---------------------------------------------------------------------------
// Launch 3: exclusive scan of block sums (single block)
// ---------------------------------------------------------------------------
__global__ void scan2_kernel(int* __restrict__ bsum, int nb) {
    __shared__ int sh[SCAN_BLOCK];
    int v = (threadIdx.x < nb) ? bsum[threadIdx.x] : 0;
    sh[threadIdx.x] = v;
    __syncthreads();
    #pragma unroll
    for (int d = 1; d < SCAN_BLOCK; d <<= 1) {
        int t = (threadIdx.x >= d) ? sh[threadIdx.x - d] : 0;
        __syncthreads();
        sh[threadIdx.x] += t;
        __syncthreads();
    }
    if (threadIdx.x < nb) bsum[threadIdx.x] = sh[threadIdx.x] - v;  // exclusive
}

// ---------------------------------------------------------------------------
// Launch 4: permute edges into CSR order (global offset = local + bsum)
// ---------------------------------------------------------------------------
__global__ void permute_kernel(const int* __restrict__ rows,
                               const int* __restrict__ cols,
                               const float* __restrict__ vals,
                               int* __restrict__ pos,
                               const int* __restrict__ bsum,
                               int2* __restrict__ pair) {
    int e = blockIdx.x * blockDim.x + threadIdx.x;
    if (e >= N_EDGES) return;
    int r = rows[e];
    int p = atomicAdd(&pos[r], 1) + __ldg(&bsum[r >> 10]);
    int2 pr;
    pr.x = cols[e];
    pr.y = __float_as_int(vals[e]);
    __stcs(pair + p, pr);    // streaming scatter
}

// ---------------------------------------------------------------------------
// Gather: 32B (256-bit) load with L2 evict_last (pins source rows in L2),
// unpack 16 halfs, FMA into 16 fp32 accumulators.
// ---------------------------------------------------------------------------
__device__ __forceinline__ void gather_acc(const __half* __restrict__ srcH,
                                           int col, int sub, float v,
                                           float* acc) {
    const char* p = reinterpret_cast<const char*>(srcH)
                    + ((size_t)col << 8) + (sub << 5);
    uint32_t q0, q1, q2, q3, q4, q5, q6, q7;
    asm volatile(
        "ld.global.nc.L2::evict_last.v8.b32 {%0,%1,%2,%3,%4,%5,%6,%7}, [%8];"
        : "=r"(q0), "=r"(q1), "=r"(q2), "=r"(q3),
          "=r"(q4), "=r"(q5), "=r"(q6), "=r"(q7)
        : "l"(p));
    uint32_t q[8] = {q0, q1, q2, q3, q4, q5, q6, q7};
    #pragma unroll
    for (int i = 0; i < 8; ++i) {
        __half2 h = *reinterpret_cast<__half2*>(&q[i]);
        float2 f = __half22float2(h);
        acc[2 * i]     += v * f.x;
        acc[2 * i + 1] += v * f.y;
    }
}

__device__ __forceinline__ void unpack16(uint4 lo, uint4 hi, float* f) {
    uint32_t q[8] = {lo.x, lo.y, lo.z, lo.w, hi.x, hi.y, hi.z, hi.w};
    #pragma unroll
    for (int i = 0; i < 8; ++i) {
        __half2 h = *reinterpret_cast<__half2*>(&q[i]);
        float2 t = __half22float2(h);
        f[2 * i] = t.x;
        f[2 * i + 1] = t.y;
    }
}

// ---------------------------------------------------------------------------
// Launches 5-7: pull SpMM. One 8-lane group per row; lane owns 16 elements
// (32B fp16). Gather via LDG.256 + L2::evict_last, unrolled x4. fp32 accum.
// __launch_bounds__(256, 6): cap regs at 40 -> 6 blocks/SM = 75% occupancy.
// FUSED (layer 3): out = 0.25*(x0_fp32 + A + B + y)
// ---------------------------------------------------------------------------
template <bool FUSED>
__global__ void __launch_bounds__(256, 6)
spmm_kernel(const int* __restrict__ offsetL,
            const int* __restrict__ bsum,
            const int2* __restrict__ pair,
            const __half* __restrict__ xH,    // gather src (fp16, L2-pinned)
            __half* __restrict__ dstH,        // layer output (fp16)
            const float4* __restrict__ u,     // FUSED: user embs fp32
            const float4* __restrict__ it,    // FUSED: item embs fp32
            const __half* __restrict__ accA,  // FUSED: layer-1 out
            const __half* __restrict__ accB,  // FUSED: layer-2 out
            float4* __restrict__ out) {       // FUSED: final out fp32
    int sub = threadIdx.x & 7;                            // lane within group
    int r = (blockIdx.x * blockDim.x + threadIdx.x) >> 3; // group id = row
    if (r >= N_NODES) return;

    int j = __ldg(offsetL + r) + __ldg(bsum + (r >> 10));
    int end = (r == N_NODES - 1)
                  ? N_EDGES
                  : __ldg(offsetL + r + 1) + __ldg(bsum + ((r + 1) >> 10));

    float acc[16];
    #pragma unroll
    for (int k = 0; k < 16; ++k) acc[k] = 0.f;

    // 4 independent gathers in flight per group
    #pragma unroll 1
    for (; j + 4 <= end; j += 4) {
        int2 e0 = __ldcs(pair + j);
        int2 e1 = __ldcs(pair + j + 1);
        int2 e2 = __ldcs(pair + j + 2);
        int2 e3 = __ldcs(pair + j + 3);
        gather_acc(xH, e0.x, sub, __int_as_float(e0.y), acc);
        gather_acc(xH, e1.x, sub, __int_as_float(e1.y), acc);
        gather_acc(xH, e2.x, sub, __int_as_float(e2.y), acc);
        gather_acc(xH, e3.x, sub, __int_as_float(e3.y), acc);
    }
    #pragma unroll 1
    for (; j < end; ++j) {
        int2 e0 = __ldcs(pair + j);
        gather_acc(xH, e0.x, sub, __int_as_float(e0.y), acc);
    }

    if (FUSED) {
        const uint4* aRow = reinterpret_cast<const uint4*>(accA + (size_t)r * EMB_DIM);
        const uint4* bRow = reinterpret_cast<const uint4*>(accB + (size_t)r * EMB_DIM);
        float a[16], b[16];
        unpack16(__ldcs(aRow + 2 * sub), __ldcs(aRow + 2 * sub + 1), a);
        unpack16(__ldcs(bRow + 2 * sub), __ldcs(bRow + 2 * sub + 1), b);

        const float4* xr = (r < N_USERS)
                               ? (u + (size_t)r * VEC4_PER_ROW)
                               : (it + (size_t)(r - N_USERS) * VEC4_PER_ROW);
        float4* orow = out + (size_t)r * VEC4_PER_ROW + 4 * sub;
        #pragma unroll
        for (int q = 0; q < 4; ++q) {
            float4 x0 = __ldcs(xr + 4 * sub + q);
            float4 o;
            o.x = 0.25f * (x0.x + a[4 * q + 0] + b[4 * q + 0] + acc[4 * q + 0]);
            o.y = 0.25f * (x0.y + a[4 * q + 1] + b[4 * q + 1] + acc[4 * q + 1]);
            o.z = 0.25f * (x0.z + a[4 * q + 2] + b[4 * q + 2] + acc[4 * q + 2]);
            o.w = 0.25f * (x0.w + a[4 * q + 3] + b[4 * q + 3] + acc[4 * q + 3]);
            __stcs(orow + q, o);
        }
    } else {
        uint32_t q[8];
        #pragma unroll
        for (int i = 0; i < 8; ++i) {
            __half2 h = __floats2half2_rn(acc[2 * i], acc[2 * i + 1]);
            q[i] = *reinterpret_cast<unsigned*>(&h);
        }
        uint4* drow = reinterpret_cast<uint4*>(dstH + (size_t)r * EMB_DIM) + 2 * sub;
        __stcs(drow, make_uint4(q[0], q[1], q[2], q[3]));
        __stcs(drow + 1, make_uint4(q[4], q[5], q[6], q[7]));
    }
}

extern "C" void kernel_launch(void* const* d_in, const int* in_sizes, int n_in,
                              void* d_out, int out_size) {
    const float4* emb_user = (const float4*)d_in[0];
    const float4* emb_item = (const float4*)d_in[1];
    const int* edge_row = (const int*)d_in[2];
    const int* edge_col = (const int*)d_in[3];
    const float* edge_val = (const float*)d_in[4];
    float4* out = (float4*)d_out;

    __half *X, *A, *B;
    int *count_, *offsetL_, *pos_, *bsum_;
    int2 *pair_;
    cudaGetSymbolAddress((void**)&X, g_bufX);
    cudaGetSymbolAddress((void**)&A, g_bufA);
    cudaGetSymbolAddress((void**)&B, g_bufB);
    cudaGetSymbolAddress((void**)&count_, g_count);
    cudaGetSymbolAddress((void**)&offsetL_, g_offsetL);
    cudaGetSymbolAddress((void**)&pos_, g_pos);
    cudaGetSymbolAddress((void**)&bsum_, g_bsum);
    cudaGetSymbolAddress((void**)&pair_, g_pair);

    const int T = 256;
    const int gridEdge = (N_EDGES + T - 1) / T;
    const int TS = 256;                                   // 32 rows per block
    const int gridRow = (int)(((size_t)N_NODES * 8 + TS - 1) / TS);

    // ---- build: histogram(+convert), two-kernel scan, permute ----
    hist_convert_kernel<<<gridEdge, T>>>(edge_row, count_,
                                         emb_user, emb_item, (uint2*)X);
    scan1_kernel<<<N_SCAN_BLOCKS, SCAN_BLOCK>>>(count_, offsetL_, pos_, bsum_);
    scan2_kernel<<<1, SCAN_BLOCK>>>(bsum_, N_SCAN_BLOCKS);
    permute_kernel<<<gridEdge, T>>>(edge_row, edge_col, edge_val,
                                    pos_, bsum_, pair_);

    // ---- Layer 1: gather X -> A ----
    spmm_kernel<false><<<gridRow, TS>>>(offsetL_, bsum_, pair_, X, A,
                                        nullptr, nullptr, nullptr, nullptr,
                                        nullptr);
    // ---- Layer 2: gather A -> B ----
    spmm_kernel<false><<<gridRow, TS>>>(offsetL_, bsum_, pair_, A, B,
                                        nullptr, nullptr, nullptr, nullptr,
                                        nullptr);
    // ---- Layer 3 fused: gather B, out = 0.25*(x0 + A + B + y) ----
    spmm_kernel<true><<<gridRow, TS>>>(offsetL_, bsum_, pair_, B, nullptr,
                                       emb_user, emb_item, A, B, out);
}